// round 1
// baseline (speedup 1.0000x reference)
#include <cuda_runtime.h>
#include <cuda_bf16.h>

// bow_labeler: masked mean-pool over L, then 14 small linear heads (54 outputs).
// B=256, L=512, D=768.
// Inputs (metadata order):
//   d_in[0] final_hidden   [256,512,768] f32
//   d_in[1] attention_mask [256,512]     i32
//   d_in[2] W13            [13,4,768]    f32   (52 rows of 768)
//   d_in[3] b13            [13,4]        f32   (52)
//   d_in[4] W14            [2,768]       f32
//   d_in[5] b14            [2]           f32
// Output: [256, 54] f32  (13*4 concat 2)

#define B_DIM 256
#define L_DIM 512
#define D_DIM 768
#define N_OUT 54

__global__ __launch_bounds__(D_DIM) void bow_labeler_kernel(
    const float* __restrict__ fh,
    const int*   __restrict__ mask,
    const float* __restrict__ W13,
    const float* __restrict__ b13,
    const float* __restrict__ W14,
    const float* __restrict__ b14,
    float*       __restrict__ out)
{
    const int b   = blockIdx.x;
    const int tid = threadIdx.x;
    const int lane = tid & 31;
    const int warp = tid >> 5;

    __shared__ float s_pooled[D_DIM];
    __shared__ int   s_mask[L_DIM];
    __shared__ float s_invcnt;

    // Stage the mask row.
    if (tid < L_DIM) s_mask[tid] = mask[b * L_DIM + tid];
    __syncthreads();

    // Warp 0 counts valid tokens.
    if (warp == 0) {
        int c = 0;
        #pragma unroll
        for (int l = lane; l < L_DIM; l += 32) c += s_mask[l];
        #pragma unroll
        for (int off = 16; off; off >>= 1)
            c += __shfl_down_sync(0xffffffffu, c, off);
        if (lane == 0) s_invcnt = 1.0f / (float)c;
    }

    // Masked column sums: thread tid owns column tid. Rows with mask==0 are
    // skipped entirely (predicated loads), halving HBM traffic on average.
    // 4-way unroll keeps 4 independent loads in flight per thread.
    const float* base = fh + (size_t)b * L_DIM * D_DIM + tid;
    float a0 = 0.f, a1 = 0.f, a2 = 0.f, a3 = 0.f;
    #pragma unroll 1
    for (int l = 0; l < L_DIM; l += 4) {
        if (s_mask[l + 0]) a0 += base[(size_t)(l + 0) * D_DIM];
        if (s_mask[l + 1]) a1 += base[(size_t)(l + 1) * D_DIM];
        if (s_mask[l + 2]) a2 += base[(size_t)(l + 2) * D_DIM];
        if (s_mask[l + 3]) a3 += base[(size_t)(l + 3) * D_DIM];
    }
    float acc = (a0 + a1) + (a2 + a3);

    __syncthreads();  // ensure s_invcnt written (warp0) before use
    s_pooled[tid] = acc * s_invcnt;
    __syncthreads();

    // Heads: 54 dot-products of length 768 against pooled. One output per
    // warp, strided over 24 warps (outputs 0..51 -> W13/b13, 52..53 -> W14/b14).
    for (int o = warp; o < N_OUT; o += 24) {
        const float* w   = (o < 52) ? (W13 + (size_t)o * D_DIM)
                                    : (W14 + (size_t)(o - 52) * D_DIM);
        const float bias = (o < 52) ? b13[o] : b14[o - 52];
        float sum = 0.f;
        #pragma unroll
        for (int d = lane; d < D_DIM; d += 32)
            sum += s_pooled[d] * w[d];
        #pragma unroll
        for (int off = 16; off; off >>= 1)
            sum += __shfl_down_sync(0xffffffffu, sum, off);
        if (lane == 0) out[b * N_OUT + o] = sum + bias;
    }
}

extern "C" void kernel_launch(void* const* d_in, const int* in_sizes, int n_in,
                              void* d_out, int out_size)
{
    const float* fh   = (const float*)d_in[0];
    const int*   mask = (const int*)d_in[1];
    const float* W13  = (const float*)d_in[2];
    const float* b13  = (const float*)d_in[3];
    const float* W14  = (const float*)d_in[4];
    const float* b14  = (const float*)d_in[5];
    float* out = (float*)d_out;

    bow_labeler_kernel<<<B_DIM, D_DIM>>>(fh, mask, W13, b13, W14, b14, out);
}

// round 2
// speedup vs baseline: 2.4934x; 2.4934x over previous
#include <cuda_runtime.h>
#include <cuda_bf16.h>

// bow_labeler: masked mean-pool over L, then 14 small linear heads (54 outputs).
// B=256, L=512, D=768.
// Two-phase: (1) masked partial column sums over L-chunks (BW-bound streaming),
//            (2) reduce partials + normalize + 54-head GEMV epilogue.

#define B_DIM   256
#define L_DIM   512
#define D_DIM   768
#define N_OUT   54
#define SPLIT   4
#define L_CHUNK (L_DIM / SPLIT)   // 128
#define D4      (D_DIM / 4)       // 192 float4 per row
#define T1      384               // kernel1 block: 192 cols x 2 rows

// Scratch for partial sums: [B][SPLIT][D] floats = 3 MB.
__device__ float g_partial[B_DIM * SPLIT * D_DIM];

__global__ __launch_bounds__(T1) void pool_partial_kernel(
    const float* __restrict__ fh,
    const int*   __restrict__ mask)
{
    const int b   = blockIdx.x;
    const int s   = blockIdx.y;
    const int tid = threadIdx.x;
    const int c4  = tid % D4;      // float4 column index 0..191
    const int r   = tid / D4;      // row phase 0/1

    __shared__ int    s_mask[L_CHUNK];
    __shared__ float4 s_red[D4];

    if (tid < L_CHUNK) s_mask[tid] = mask[b * L_DIM + s * L_CHUNK + tid];
    __syncthreads();

    const float4* base = (const float4*)(fh + ((size_t)b * L_DIM + (size_t)s * L_CHUNK) * D_DIM) + c4;

    // Each thread covers rows r, r+2, r+4, ... within the 128-row chunk.
    // Two accumulators + unroll keep >=4 independent 16B loads in flight.
    float4 accA = make_float4(0.f, 0.f, 0.f, 0.f);
    float4 accB = make_float4(0.f, 0.f, 0.f, 0.f);
    #pragma unroll 4
    for (int l = r; l < L_CHUNK; l += 4) {
        if (s_mask[l]) {
            float4 v = base[(size_t)l * D4];
            accA.x += v.x; accA.y += v.y; accA.z += v.z; accA.w += v.w;
        }
        if (s_mask[l + 2]) {
            float4 v = base[(size_t)(l + 2) * D4];
            accB.x += v.x; accB.y += v.y; accB.z += v.z; accB.w += v.w;
        }
    }
    accA.x += accB.x; accA.y += accB.y; accA.z += accB.z; accA.w += accB.w;

    // Combine the two row-phases.
    if (r == 1) s_red[c4] = accA;
    __syncthreads();
    if (r == 0) {
        float4 o = s_red[c4];
        accA.x += o.x; accA.y += o.y; accA.z += o.z; accA.w += o.w;
        float4* dst = (float4*)(g_partial + ((size_t)b * SPLIT + s) * D_DIM);
        dst[c4] = accA;
    }
}

__global__ __launch_bounds__(D_DIM) void heads_kernel(
    const int*   __restrict__ mask,
    const float* __restrict__ W13,
    const float* __restrict__ b13,
    const float* __restrict__ W14,
    const float* __restrict__ b14,
    float*       __restrict__ out)
{
    const int b    = blockIdx.x;
    const int tid  = threadIdx.x;
    const int lane = tid & 31;
    const int warp = tid >> 5;

    __shared__ float s_pooled[D_DIM];
    __shared__ int   s_cnt;
    __shared__ float s_invcnt;

    if (tid == 0) s_cnt = 0;
    __syncthreads();

    // Count valid tokens (512 loads across first 16 warps, warp-reduced).
    if (tid < L_DIM) {
        int m = mask[b * L_DIM + tid];
        #pragma unroll
        for (int off = 16; off; off >>= 1)
            m += __shfl_down_sync(0xffffffffu, m, off);
        if (lane == 0) atomicAdd(&s_cnt, m);
    }

    // Reduce the 4 partials for this column.
    const float* p = g_partial + (size_t)b * SPLIT * D_DIM + tid;
    float sum = p[0] + p[D_DIM] + p[2 * D_DIM] + p[3 * D_DIM];

    __syncthreads();
    if (tid == 0) s_invcnt = 1.0f / (float)s_cnt;
    __syncthreads();

    s_pooled[tid] = sum * s_invcnt;
    __syncthreads();

    // 54 dot-products of length 768; one output per warp, strided over 24 warps.
    for (int o = warp; o < N_OUT; o += 24) {
        const float* w   = (o < 52) ? (W13 + (size_t)o * D_DIM)
                                    : (W14 + (size_t)(o - 52) * D_DIM);
        const float bias = (o < 52) ? b13[o] : b14[o - 52];
        float acc = 0.f;
        #pragma unroll
        for (int d = lane; d < D_DIM; d += 32)
            acc += s_pooled[d] * w[d];
        #pragma unroll
        for (int off = 16; off; off >>= 1)
            acc += __shfl_down_sync(0xffffffffu, acc, off);
        if (lane == 0) out[b * N_OUT + o] = acc + bias;
    }
}

extern "C" void kernel_launch(void* const* d_in, const int* in_sizes, int n_in,
                              void* d_out, int out_size)
{
    const float* fh   = (const float*)d_in[0];
    const int*   mask = (const int*)d_in[1];
    const float* W13  = (const float*)d_in[2];
    const float* b13  = (const float*)d_in[3];
    const float* W14  = (const float*)d_in[4];
    const float* b14  = (const float*)d_in[5];
    float* out = (float*)d_out;

    dim3 grid1(B_DIM, SPLIT);
    pool_partial_kernel<<<grid1, T1>>>(fh, mask);
    heads_kernel<<<B_DIM, D_DIM>>>(mask, W13, b13, W14, b14, out);
}

// round 3
// speedup vs baseline: 2.9993x; 1.2029x over previous
#include <cuda_runtime.h>
#include <cuda_bf16.h>

// bow_labeler: masked mean-pool over L, then 14 small linear heads (54 outputs).
// B=256, L=512, D=768.
// Phase 1: masked partial column sums over 64-row L-chunks (BW-bound stream).
// Phase 2: reduce 8 partials + normalize + 54-head GEMV, fully float4.

#define B_DIM   256
#define L_DIM   512
#define D_DIM   768
#define N_OUT   54
#define SPLIT   8
#define L_CHUNK (L_DIM / SPLIT)   // 64
#define D4      (D_DIM / 4)       // 192 float4 per row
#define T1      192               // kernel1: one thread per float4 column
#define T2      512

// Scratch for partial sums: [B][SPLIT][D] floats = 6 MB.
__device__ float g_partial[B_DIM * SPLIT * D_DIM];

__device__ __forceinline__ void f4acc(float4& a, const float4& v) {
    a.x += v.x; a.y += v.y; a.z += v.z; a.w += v.w;
}

__global__ __launch_bounds__(T1) void pool_partial_kernel(
    const float* __restrict__ fh,
    const int*   __restrict__ mask)
{
    const int b   = blockIdx.x;
    const int s   = blockIdx.y;
    const int c4  = threadIdx.x;   // float4 column 0..191

    __shared__ int s_mask[L_CHUNK];

    if (c4 < L_CHUNK) s_mask[c4] = mask[b * L_DIM + s * L_CHUNK + c4];
    __syncthreads();

    const float4* base =
        (const float4*)(fh + ((size_t)b * L_DIM + (size_t)s * L_CHUNK) * D_DIM) + c4;

    // 64 rows per chunk; 8 guarded independent loads per unrolled body.
    float4 a0 = make_float4(0.f,0.f,0.f,0.f);
    float4 a1 = make_float4(0.f,0.f,0.f,0.f);
    float4 a2 = make_float4(0.f,0.f,0.f,0.f);
    float4 a3 = make_float4(0.f,0.f,0.f,0.f);
    #pragma unroll 1
    for (int l = 0; l < L_CHUNK; l += 8) {
        if (s_mask[l+0]) f4acc(a0, base[(size_t)(l+0) * D4]);
        if (s_mask[l+1]) f4acc(a1, base[(size_t)(l+1) * D4]);
        if (s_mask[l+2]) f4acc(a2, base[(size_t)(l+2) * D4]);
        if (s_mask[l+3]) f4acc(a3, base[(size_t)(l+3) * D4]);
        if (s_mask[l+4]) f4acc(a0, base[(size_t)(l+4) * D4]);
        if (s_mask[l+5]) f4acc(a1, base[(size_t)(l+5) * D4]);
        if (s_mask[l+6]) f4acc(a2, base[(size_t)(l+6) * D4]);
        if (s_mask[l+7]) f4acc(a3, base[(size_t)(l+7) * D4]);
    }
    f4acc(a0, a1); f4acc(a2, a3); f4acc(a0, a2);

    float4* dst = (float4*)(g_partial + ((size_t)b * SPLIT + s) * D_DIM);
    dst[c4] = a0;
}

__global__ __launch_bounds__(T2) void heads_kernel(
    const int*   __restrict__ mask,
    const float* __restrict__ W13,
    const float* __restrict__ b13,
    const float* __restrict__ W14,
    const float* __restrict__ b14,
    float*       __restrict__ out)
{
    const int b    = blockIdx.x;
    const int tid  = threadIdx.x;
    const int lane = tid & 31;
    const int warp = tid >> 5;

    __shared__ float4 s_pooled[D4];
    __shared__ int    s_cnt;
    __shared__ float  s_invcnt;

    if (tid == 0) s_cnt = 0;
    __syncthreads();

    // Count valid tokens: 512 threads, one mask element each.
    {
        int m = mask[b * L_DIM + tid];
        #pragma unroll
        for (int off = 16; off; off >>= 1)
            m += __shfl_down_sync(0xffffffffu, m, off);
        if (lane == 0) atomicAdd(&s_cnt, m);
    }

    // Threads 0..191 reduce the 8 partials for their float4 column (8
    // independent 16B loads in flight).
    float4 colsum = make_float4(0.f,0.f,0.f,0.f);
    if (tid < D4) {
        const float4* gp4 = (const float4*)(g_partial + (size_t)b * SPLIT * D_DIM);
        #pragma unroll
        for (int s = 0; s < SPLIT; s++)
            f4acc(colsum, gp4[(size_t)s * D4 + tid]);
    }

    __syncthreads();
    if (tid == 0) s_invcnt = 1.0f / (float)s_cnt;
    __syncthreads();

    if (tid < D4) {
        float inv = s_invcnt;
        colsum.x *= inv; colsum.y *= inv; colsum.z *= inv; colsum.w *= inv;
        s_pooled[tid] = colsum;
    }
    __syncthreads();

    // 54 outputs over 16 warps; per output each lane does 6 LDG.128 + 6
    // LDS.128 + 24 FMA, then a warp shuffle reduce.
    for (int o = warp; o < N_OUT; o += (T2 / 32)) {
        const float4* w4  = (const float4*)((o < 52) ? (W13 + (size_t)o * D_DIM)
                                                     : (W14 + (size_t)(o - 52) * D_DIM));
        const float bias  = (o < 52) ? b13[o] : b14[o - 52];
        float acc = 0.f;
        #pragma unroll
        for (int i = 0; i < D4 / 32; i++) {
            float4 w = w4[lane + 32 * i];
            float4 p = s_pooled[lane + 32 * i];
            acc += w.x * p.x + w.y * p.y + w.z * p.z + w.w * p.w;
        }
        #pragma unroll
        for (int off = 16; off; off >>= 1)
            acc += __shfl_down_sync(0xffffffffu, acc, off);
        if (lane == 0) out[b * N_OUT + o] = acc + bias;
    }
}

extern "C" void kernel_launch(void* const* d_in, const int* in_sizes, int n_in,
                              void* d_out, int out_size)
{
    const float* fh   = (const float*)d_in[0];
    const int*   mask = (const int*)d_in[1];
    const float* W13  = (const float*)d_in[2];
    const float* b13  = (const float*)d_in[3];
    const float* W14  = (const float*)d_in[4];
    const float* b14  = (const float*)d_in[5];
    float* out = (float*)d_out;

    dim3 grid1(B_DIM, SPLIT);
    pool_partial_kernel<<<grid1, T1>>>(fh, mask);
    heads_kernel<<<B_DIM, T2>>>(mask, W13, b13, W14, b14, out);
}